// round 14
// baseline (speedup 1.0000x reference)
#include <cuda_runtime.h>
#include <cuda_bf16.h>
#include <stdint.h>

#define B_  2
#define T_  2048
#define S_  2048
#define E_  1024
#define H_  16
#define D_  64
#define BT  (B_*T_)
#define Z_  (B_*H_)
#define SCALE 0.125f

typedef __nv_bfloat16 bf16;

// Scratch (__device__ globals; allocation-free rule)
__device__ bf16 g_Th[(size_t)BT*E_], g_Tl[(size_t)BT*E_];
__device__ bf16 g_Sh[(size_t)BT*E_], g_Sl[(size_t)BT*E_];
__device__ bf16 g_Wqh[(size_t)E_*E_], g_Wql[(size_t)E_*E_];
__device__ bf16 g_Wkh[(size_t)E_*E_], g_Wkl[(size_t)E_*E_];
__device__ bf16 g_Wvh[(size_t)E_*E_], g_Wvl[(size_t)E_*E_];
__device__ bf16 g_Woh[(size_t)E_*E_], g_Wol[(size_t)E_*E_];
__device__ bf16 g_Qh[(size_t)Z_*T_*D_], g_Ql[(size_t)Z_*T_*D_];
__device__ bf16 g_Kh[(size_t)Z_*S_*D_], g_Kl[(size_t)Z_*S_*D_];
__device__ bf16 g_Vh[(size_t)Z_*S_*D_], g_Vl[(size_t)Z_*S_*D_];
__device__ bf16 g_Ch[(size_t)BT*E_], g_Cl[(size_t)BT*E_];

__device__ __forceinline__ uint32_t smem_u32(const void* p) {
    return (uint32_t)__cvta_generic_to_shared(p);
}
__device__ __forceinline__ void cvt_hilo2(float x0, float x1, uint32_t& h, uint32_t& l) {
    asm("cvt.rn.bf16x2.f32 %0, %1, %2;" : "=r"(h) : "f"(x1), "f"(x0));
    float h0 = __uint_as_float(h << 16);
    float h1 = __uint_as_float(h & 0xffff0000u);
    asm("cvt.rn.bf16x2.f32 %0, %1, %2;" : "=r"(l) : "f"(x1 - h1), "f"(x0 - h0));
}
__device__ __forceinline__ void mma16816(float c[4], const uint32_t a[4], const uint32_t b[2]) {
    asm volatile("mma.sync.aligned.m16n8k16.row.col.f32.bf16.bf16.f32 "
        "{%0,%1,%2,%3}, {%4,%5,%6,%7}, {%8,%9}, {%0,%1,%2,%3};"
        : "+f"(c[0]), "+f"(c[1]), "+f"(c[2]), "+f"(c[3])
        : "r"(a[0]), "r"(a[1]), "r"(a[2]), "r"(a[3]), "r"(b[0]), "r"(b[1]));
}
__device__ __forceinline__ void ldsm4(uint32_t r[4], uint32_t a) {
    asm volatile("ldmatrix.sync.aligned.m8n8.x4.shared.b16 {%0,%1,%2,%3}, [%4];"
        : "=r"(r[0]), "=r"(r[1]), "=r"(r[2]), "=r"(r[3]) : "r"(a));
}
__device__ __forceinline__ void ldsm4t(uint32_t r[4], uint32_t a) {
    asm volatile("ldmatrix.sync.aligned.m8n8.x4.trans.shared.b16 {%0,%1,%2,%3}, [%4];"
        : "=r"(r[0]), "=r"(r[1]), "=r"(r[2]), "=r"(r[3]) : "r"(a));
}
__device__ __forceinline__ void cpa16p(const void* smem, const void* g) {
    asm volatile("cp.async.cg.shared.global [%0], [%1], 16;"
                 :: "r"(smem_u32(smem)), "l"(g));
}
__device__ __forceinline__ void cp_commit() { asm volatile("cp.async.commit_group;"); }
template<int N> __device__ __forceinline__ void cp_wait() {
    asm volatile("cp.async.wait_group %0;" :: "n"(N));
}
__device__ __forceinline__ float fast_exp_s(float x) {
    const float MAGIC = 12582912.0f;
    float t = x * (1.44269504088896f * SCALE);
    float r = t + MAGIC;
    int ib = __float_as_int(r);
    float f = t - (r - MAGIC);
    float p = 9.6181291e-3f;
    p = fmaf(p, f, 5.5504109e-2f);
    p = fmaf(p, f, 2.4022651e-1f);
    p = fmaf(p, f, 6.9314718e-1f);
    p = fmaf(p, f, 1.0f);
    return p * __int_as_float((ib + 127) << 23);
}

// ---------------------------------------------------------------------------
// Batched fp32 -> bf16 hi/lo converter
// ---------------------------------------------------------------------------
struct CvtArgs {
    const float* in[6];
    bf16* oh[6];
    bf16* ol[6];
    int n4[6];
};

__global__ void k_cvt6(CvtArgs a)
{
    const int z = blockIdx.z;
    int i = blockIdx.x * blockDim.x + threadIdx.x;
    if (i >= a.n4[z]) return;
    float4 v = ((const float4*)a.in[z])[i];
    uint32_t h01, l01, h23, l23;
    cvt_hilo2(v.x, v.y, h01, l01);
    cvt_hilo2(v.z, v.w, h23, l23);
    ((uint2*)a.oh[z])[i] = make_uint2(h01, h23);
    ((uint2*)a.ol[z])[i] = make_uint2(l01, l23);
}

// ---------------------------------------------------------------------------
// GEMM core (NT, 128x128x32, cp.async 2-stage, ldmatrix, bf16x3) — unchanged
// ---------------------------------------------------------------------------
#define PLD 40
#define PSZ (128*PLD)

template<bool TO_HL>
__device__ __forceinline__ void proj_core(
    const bf16* __restrict__ Agh, const bf16* __restrict__ Agl,
    const bf16* __restrict__ Bgh, const bf16* __restrict__ Bgl,
    float* __restrict__ C, const float* __restrict__ bias,
    bf16* __restrict__ Oh, bf16* __restrict__ Ol)
{
    extern __shared__ bf16 sm[];
    bf16* Ah = sm;
    bf16* Al = sm + 2 * PSZ;
    bf16* Bh = sm + 4 * PSZ;
    bf16* Bl = sm + 6 * PSZ;

    const int tid = threadIdx.x, lane = tid & 31, wid = tid >> 5;
    const int wm = wid >> 2, wn = wid & 3;
    const int bm = blockIdx.y * 128, bn = blockIdx.x * 128;
    const int rr = lane >> 2, q2 = (lane & 3) << 1;

    const int lrow = lane & 15, lkof = (lane >> 4) << 3;
    const int brow = ((lane >> 4) << 3) + (lane & 7);
    const int bkof = ((lane >> 3) & 1) << 3;

    auto issue = [&](int t, int buf) {
        const size_t k0 = (size_t)t * 32;
        #pragma unroll
        for (int i = 0; i < 2; i++) {
            int j = tid + i * 256;
            int r = j >> 2, c = (j & 3) << 3;
            size_t ga = (size_t)(bm + r) * E_ + k0 + c;
            size_t gb = (size_t)(bn + r) * E_ + k0 + c;
            int so = buf * PSZ + r * PLD + c;
            cpa16p(&Ah[so], &Agh[ga]);
            cpa16p(&Al[so], &Agl[ga]);
            cpa16p(&Bh[so], &Bgh[gb]);
            cpa16p(&Bl[so], &Bgl[gb]);
        }
        cp_commit();
    };

    float acc[4][4][4] = {};

    issue(0, 0);
    for (int t = 0; t < 32; t++) {
        const int buf = t & 1;
        if (t < 31) { issue(t + 1, buf ^ 1); cp_wait<1>(); }
        else cp_wait<0>();
        __syncthreads();

        const int bofs = buf * PSZ;
        uint32_t aAh[4], aAl[4];
        #pragma unroll
        for (int mt = 0; mt < 4; mt++) {
            int m = wm * 64 + mt * 16 + lrow;
            aAh[mt] = smem_u32(&Ah[bofs + m * PLD + lkof]);
            aAl[mt] = smem_u32(&Al[bofs + m * PLD + lkof]);
        }
        uint32_t aBh[2], aBl[2];
        #pragma unroll
        for (int ng = 0; ng < 2; ng++) {
            int n = wn * 32 + ng * 16 + brow;
            aBh[ng] = smem_u32(&Bh[bofs + n * PLD + bkof]);
            aBl[ng] = smem_u32(&Bl[bofs + n * PLD + bkof]);
        }

        #pragma unroll
        for (int ks = 0; ks < 2; ks++) {
            const uint32_t kb = ks * 32;
            uint32_t bh4[2][4], bl4[2][4];
            #pragma unroll
            for (int ng = 0; ng < 2; ng++) {
                ldsm4(bh4[ng], aBh[ng] + kb);
                ldsm4(bl4[ng], aBl[ng] + kb);
            }
            #pragma unroll
            for (int mt = 0; mt < 4; mt++) {
                uint32_t ah[4], al[4];
                ldsm4(ah, aAh[mt] + kb);
                ldsm4(al, aAl[mt] + kb);
                #pragma unroll
                for (int nt = 0; nt < 4; nt++) {
                    const int ng = nt >> 1, s = (nt & 1) << 1;
                    uint32_t bh[2] = { bh4[ng][s], bh4[ng][s + 1] };
                    uint32_t bl[2] = { bl4[ng][s], bl4[ng][s + 1] };
                    mma16816(acc[mt][nt], ah, bh);
                    mma16816(acc[mt][nt], al, bh);
                    mma16816(acc[mt][nt], ah, bl);
                }
            }
        }
        __syncthreads();
    }

    #pragma unroll
    for (int mt = 0; mt < 4; mt++) {
        #pragma unroll
        for (int nt = 0; nt < 4; nt++) {
            int n = bn + wn * 32 + nt * 8 + q2;
            #pragma unroll
            for (int rh = 0; rh < 2; rh++) {
                int m = bm + wm * 64 + mt * 16 + rr + rh * 8;
                float v0 = acc[mt][nt][rh * 2 + 0];
                float v1 = acc[mt][nt][rh * 2 + 1];
                if (TO_HL) {
                    int b = m >> 11, t = m & 2047;
                    int h = n >> 6, d = n & 63;
                    size_t off = ((size_t)(b * H_ + h) * T_ + t) * D_ + d;
                    uint32_t hh, ll;
                    cvt_hilo2(v0, v1, hh, ll);
                    *(uint32_t*)&Oh[off] = hh;
                    *(uint32_t*)&Ol[off] = ll;
                } else {
                    float* p = C + (size_t)m * E_ + n;
                    p[0] = v0 + bias[n];
                    p[1] = v1 + bias[n + 1];
                }
            }
        }
    }
}

__global__ __launch_bounds__(256, 2) void k_proj3(
    const bf16* __restrict__ Th, const bf16* __restrict__ Tl,
    const bf16* __restrict__ Sh, const bf16* __restrict__ Sl,
    const bf16* __restrict__ Wqh, const bf16* __restrict__ Wql,
    const bf16* __restrict__ Wkh, const bf16* __restrict__ Wkl,
    const bf16* __restrict__ Wvh, const bf16* __restrict__ Wvl,
    bf16* __restrict__ Qh, bf16* __restrict__ Ql,
    bf16* __restrict__ Kh, bf16* __restrict__ Kl,
    bf16* __restrict__ Vh, bf16* __restrict__ Vl)
{
    const int z = blockIdx.z;
    const bf16* Agh = (z == 0) ? Th : Sh;
    const bf16* Agl = (z == 0) ? Tl : Sl;
    const bf16* Bgh = (z == 0) ? Wqh : (z == 1) ? Wkh : Wvh;
    const bf16* Bgl = (z == 0) ? Wql : (z == 1) ? Wkl : Wvl;
    bf16* Oh = (z == 0) ? Qh : (z == 1) ? Kh : Vh;
    bf16* Ol = (z == 0) ? Ql : (z == 1) ? Kl : Vl;
    proj_core<true>(Agh, Agl, Bgh, Bgl, nullptr, nullptr, Oh, Ol);
}

__global__ __launch_bounds__(256, 2) void k_projo(
    const bf16* __restrict__ Agh, const bf16* __restrict__ Agl,
    const bf16* __restrict__ Bgh, const bf16* __restrict__ Bgl,
    float* __restrict__ C, const float* __restrict__ bias)
{
    proj_core<false>(Agh, Agl, Bgh, Bgl, C, bias, nullptr, nullptr);
}

// ---------------------------------------------------------------------------
// Fused attention, 512 threads (16 warps). Warp tile: 16 t-rows x 64 s-cols.
// Pass 1: S=Qh*Kh (1 MMA), exp, row sums. Kh double-buffered in K regions.
// Pass 2: full bf16x3 S, p=e*inv_rs, write final attn once, PV from register
//         P-fragments; K/V single-buffered with split prefetch. 2-way ctx
//         reduction via smem atomics.
// ---------------------------------------------------------------------------
#define LDQ 72
#define QSZ (128*LDQ)
#define ATT_SMEM (6*QSZ*(int)sizeof(bf16))   // 110592

__global__ __launch_bounds__(512) void k_att(float* __restrict__ attn)
{
    extern __shared__ bf16 sm[];
    bf16* Qh = sm;
    bf16* Ql = sm + QSZ;
    bf16* Kh = sm + 2 * QSZ;
    bf16* Kl = sm + 3 * QSZ;
    bf16* Vh = sm + 4 * QSZ;
    bf16* Vl = sm + 5 * QSZ;
    __shared__ float rs[128];

    const int tid = threadIdx.x, lane = tid & 31, wid = tid >> 5;
    const int wm = wid >> 1, wn = wid & 1;           // 8 x 2 warps
    const int rr = lane >> 2, q2 = (lane & 3) << 1;
    const int z = blockIdx.y, t0 = blockIdx.x * 128;
    const int b = z >> 4, h = z & 15;

    const int lrow = lane & 15, lkof = (lane >> 4) << 3;
    const int brow = ((lane >> 4) << 3) + (lane & 7);
    const int bkof = ((lane >> 3) & 1) << 3;
    const int vkrow = ((lane >> 3) & 1) * 8 + (lane & 7);
    const int vncol = (lane >> 4) << 3;

    const bf16* Qhg = g_Qh + ((size_t)z * T_ + t0) * D_;
    const bf16* Qlg = g_Ql + ((size_t)z * T_ + t0) * D_;
    const bf16* Khg = g_Kh + (size_t)z * S_ * D_;
    const bf16* Klg = g_Kl + (size_t)z * S_ * D_;
    const bf16* Vhg = g_Vh + (size_t)z * S_ * D_;
    const bf16* Vlg = g_Vl + (size_t)z * S_ * D_;
    float* Ab = attn + (size_t)z * T_ * S_;

    if (tid < 128) rs[tid] = 0.f;

    #pragma unroll
    for (int i = 0; i < 2; i++) {
        int idx = tid + i * 512;
        int r = idx >> 3, c = (idx & 7) << 3;
        *(uint4*)&Qh[r * LDQ + c] = *(const uint4*)&Qhg[r * D_ + c];
        *(uint4*)&Ql[r * LDQ + c] = *(const uint4*)&Qlg[r * D_ + c];
    }

    // pass 1: Kh only, ring over {Kh, Kl} regions
    auto issueK1 = [&](int si, int buf) {
        const bf16* Kt = Khg + (size_t)si * 128 * D_;
        bf16* base = buf ? Kl : Kh;
        #pragma unroll
        for (int i = 0; i < 2; i++) {
            int j = tid + i * 512;
            int r = j >> 3, c = (j & 7) << 3;
            cpa16p(&base[r * LDQ + c], &Kt[r * D_ + c]);
        }
        cp_commit();
    };
    auto issueK2 = [&](int si) {
        const bf16* Kt = Khg + (size_t)si * 128 * D_;
        const bf16* Lt = Klg + (size_t)si * 128 * D_;
        #pragma unroll
        for (int i = 0; i < 2; i++) {
            int j = tid + i * 512;
            int r = j >> 3, c = (j & 7) << 3;
            cpa16p(&Kh[r * LDQ + c], &Kt[r * D_ + c]);
            cpa16p(&Kl[r * LDQ + c], &Lt[r * D_ + c]);
        }
        cp_commit();
    };
    auto issueV2 = [&](int si) {
        const bf16* Vt = Vhg + (size_t)si * 128 * D_;
        const bf16* Wt = Vlg + (size_t)si * 128 * D_;
        #pragma unroll
        for (int i = 0; i < 2; i++) {
            int j = tid + i * 512;
            int r = j >> 3, c = (j & 7) << 3;
            cpa16p(&Vh[r * LDQ + c], &Vt[r * D_ + c]);
            cpa16p(&Vl[r * LDQ + c], &Wt[r * D_ + c]);
        }
        cp_commit();
    };

    const uint32_t aQh = smem_u32(&Qh[(wm * 16 + lrow) * LDQ + lkof]);
    const uint32_t aQl = smem_u32(&Ql[(wm * 16 + lrow) * LDQ + lkof]);

    // =================== PASS 1: row sums (1-MMA QK) ===================
    float psum[2] = {0.f, 0.f};
    issueK1(0, 0);
    for (int si = 0; si < 16; si++) {
        const int buf = si & 1;
        if (si < 15) { issueK1(si + 1, buf ^ 1); cp_wait<1>(); }
        else cp_wait<0>();
        __syncthreads();

        const bf16* base = buf ? Kl : Kh;
        uint32_t aKh[4];
        #pragma unroll
        for (int ng = 0; ng < 4; ng++) {
            int n = wn * 64 + ng * 16 + brow;
            aKh[ng] = smem_u32(&base[n * LDQ + bkof]);
        }

        float acc[8][4] = {};
        #pragma unroll
        for (int ks = 0; ks < 4; ks++) {
            const uint32_t kb = ks * 32;
            uint32_t ah[4];
            ldsm4(ah, aQh + kb);
            #pragma unroll
            for (int ng = 0; ng < 4; ng++) {
                uint32_t bh4[4];
                ldsm4(bh4, aKh[ng] + kb);
                #pragma unroll
                for (int s = 0; s < 2; s++) {
                    uint32_t bh[2] = { bh4[2 * s], bh4[2 * s + 1] };
                    mma16816(acc[ng * 2 + s], ah, bh);
                }
            }
        }

        #pragma unroll
        for (int nt = 0; nt < 8; nt++) {
            psum[0] += fast_exp_s(acc[nt][0]) + fast_exp_s(acc[nt][1]);
            psum[1] += fast_exp_s(acc[nt][2]) + fast_exp_s(acc[nt][3]);
        }
        __syncthreads();
    }

    atomicAdd(&rs[wm * 16 + rr], psum[0]);
    atomicAdd(&rs[wm * 16 + rr + 8], psum[1]);
    __syncthreads();
    if (tid < 128) rs[tid] = 1.0f / rs[tid];
    __syncthreads();

    // =================== PASS 2: attn write + PV ===================
    float ctx[8][4] = {};
    issueK2(0);
    issueV2(0);
    const uint32_t vbase = smem_u32(Vh);
    const uint32_t lbase = smem_u32(Vl);

    for (int si = 0; si < 16; si++) {
        cp_wait<0>();
        __syncthreads();

        uint32_t aKh[4], aKl[4];
        #pragma unroll
        for (int ng = 0; ng < 4; ng++) {
            int n = wn * 64 + ng * 16 + brow;
            aKh[ng] = smem_u32(&Kh[n * LDQ + bkof]);
            aKl[ng] = smem_u32(&Kl[n * LDQ + bkof]);
        }

        float acc[8][4] = {};
        #pragma unroll
        for (int ks = 0; ks < 4; ks++) {
            const uint32_t kb = ks * 32;
            uint32_t ah[4], al[4];
            ldsm4(ah, aQh + kb);
            ldsm4(al, aQl + kb);
            #pragma unroll
            for (int ng = 0; ng < 4; ng++) {
                uint32_t bh4[4], bl4[4];
                ldsm4(bh4, aKh[ng] + kb);
                ldsm4(bl4, aKl[ng] + kb);
                #pragma unroll
                for (int s = 0; s < 2; s++) {
                    const int nt = ng * 2 + s;
                    uint32_t bh[2] = { bh4[2 * s], bh4[2 * s + 1] };
                    uint32_t bl[2] = { bl4[2 * s], bl4[2 * s + 1] };
                    mma16816(acc[nt], ah, bh);
                    mma16816(acc[nt], al, bh);
                    mma16816(acc[nt], ah, bl);
                }
            }
        }

        __syncthreads();                 // K fully consumed by all warps
        if (si < 15) issueK2(si + 1);    // K prefetch hides under epilogue+PV

        // normalize + store final attn; keep p in acc
        {
            const int lr0 = wm * 16 + rr;
            const float inv0 = rs[lr0], inv1 = rs[lr0 + 8];
            const int r0 = t0 + lr0;
            #pragma unroll
            for (int nt = 0; nt < 8; nt++) {
                int n0 = si * 128 + wn * 64 + nt * 8 + q2;
                float p0 = fast_exp_s(acc[nt][0]) * inv0;
                float p1 = fast_exp_s(acc[nt][1]) * inv0;
                float p2 = fast_exp_s(acc[nt][2]) * inv1;
                float p3 = fast_exp_s(acc[nt][3]) * inv1;
                acc[nt][0] = p0; acc[nt][1] = p1;
                acc[nt][2] = p2; acc[nt][3] = p3;
                *(float2*)&Ab[(size_t)r0 * S_ + n0]       = make_float2(p0, p1);
                *(float2*)&Ab[(size_t)(r0 + 8) * S_ + n0] = make_float2(p2, p3);
            }
        }

        // PV: A-frags from register P (warp covers s-cols wn*64 + ks*16)
        #pragma unroll
        for (int ks = 0; ks < 4; ks++) {
            uint32_t pah[4], pal[4];
            cvt_hilo2(acc[2*ks][0],   acc[2*ks][1],   pah[0], pal[0]);
            cvt_hilo2(acc[2*ks][2],   acc[2*ks][3],   pah[1], pal[1]);
            cvt_hilo2(acc[2*ks+1][0], acc[2*ks+1][1], pah[2], pal[2]);
            cvt_hilo2(acc[2*ks+1][2], acc[2*ks+1][3], pah[3], pal[3]);
            const uint32_t srow = (uint32_t)(wn * 64 + ks * 16 + vkrow);
            #pragma unroll
            for (int ngd = 0; ngd < 4; ngd++) {
                const uint32_t voff = (srow * LDQ + ngd * 16 + vncol) * 2;
                uint32_t bh4[4], bl4[4];
                ldsm4t(bh4, vbase + voff);
                ldsm4t(bl4, lbase + voff);
                #pragma unroll
                for (int s = 0; s < 2; s++) {
                    const int ntd = ngd * 2 + s;
                    uint32_t bh[2] = { bh4[2 * s], bh4[2 * s + 1] };
                    uint32_t bl[2] = { bl4[2 * s], bl4[2 * s + 1] };
                    mma16816(ctx[ntd], pah, bh);
                    mma16816(ctx[ntd], pal, bh);
                    mma16816(ctx[ntd], pah, bl);
                }
            }
        }
        __syncthreads();                 // V fully consumed
        if (si < 15) issueV2(si + 1);
    }

    // ---- 2-way ctx reduction via smem atomics (red aliases K regions) ----
    float* red = (float*)Kh;             // 32KB needed; Kh+Kl = 36KB
    #pragma unroll
    for (int i = 0; i < 16; i++) red[tid + i * 512] = 0.f;
    __syncthreads();
    {
        const int lr = wm * 16 + rr;
        #pragma unroll
        for (int ntd = 0; ntd < 8; ntd++) {
            int d = ntd * 8 + q2;
            atomicAdd(&red[lr * 64 + d],           ctx[ntd][0]);
            atomicAdd(&red[lr * 64 + d + 1],       ctx[ntd][1]);
            atomicAdd(&red[(lr + 8) * 64 + d],     ctx[ntd][2]);
            atomicAdd(&red[(lr + 8) * 64 + d + 1], ctx[ntd][3]);
        }
    }
    __syncthreads();
    #pragma unroll
    for (int i = 0; i < 8; i++) {
        int idx = tid + i * 512;         // 4096 bf16x2 pairs
        int r = idx >> 5, d2 = (idx & 31) << 1;
        float c0 = red[r * 64 + d2], c1 = red[r * 64 + d2 + 1];
        uint32_t hh, ll;
        cvt_hilo2(c0, c1, hh, ll);
        size_t off = ((size_t)(b * T_ + t0 + r)) * E_ + h * D_ + d2;
        *(uint32_t*)&g_Ch[off] = hh;
        *(uint32_t*)&g_Cl[off] = ll;
    }
}

// ---------------------------------------------------------------------------
extern "C" void kernel_launch(void* const* d_in, const int* in_sizes, int n_in,
                              void* d_out, int out_size)
{
    const float* src = (const float*)d_in[0];
    const float* tgt = (const float*)d_in[1];
    const float* Wq  = (const float*)d_in[2];
    const float* Wk  = (const float*)d_in[3];
    const float* Wv  = (const float*)d_in[4];
    const float* Wo  = (const float*)d_in[5];
    const float* bo  = (const float*)d_in[6];

    float* out  = (float*)d_out;
    float* attn = out + (size_t)BT * E_;

    bf16 *Th, *Tl, *Sh, *Sl, *Wqh, *Wql, *Wkh, *Wkl, *Wvh, *Wvl, *Woh, *Wol;
    bf16 *Qh, *Ql, *Kh, *Kl, *Vh, *Vl, *Ch, *Cl;
    cudaGetSymbolAddress((void**)&Th, g_Th);   cudaGetSymbolAddress((void**)&Tl, g_Tl);
    cudaGetSymbolAddress((void**)&Sh, g_Sh);   cudaGetSymbolAddress((void**)&Sl, g_Sl);
    cudaGetSymbolAddress((void**)&Wqh, g_Wqh); cudaGetSymbolAddress((void**)&Wql, g_Wql);
    cudaGetSymbolAddress((void**)&Wkh, g_Wkh); cudaGetSymbolAddress((void**)&Wkl, g_Wkl);
    cudaGetSymbolAddress((void**)&Wvh, g_Wvh); cudaGetSymbolAddress((void**)&Wvl, g_Wvl);
    cudaGetSymbolAddress((void**)&Woh, g_Woh); cudaGetSymbolAddress((void**)&Wol, g_Wol);
    cudaGetSymbolAddress((void**)&Qh, g_Qh);   cudaGetSymbolAddress((void**)&Ql, g_Ql);
    cudaGetSymbolAddress((void**)&Kh, g_Kh);   cudaGetSymbolAddress((void**)&Kl, g_Kl);
    cudaGetSymbolAddress((void**)&Vh, g_Vh);   cudaGetSymbolAddress((void**)&Vl, g_Vl);
    cudaGetSymbolAddress((void**)&Ch, g_Ch);   cudaGetSymbolAddress((void**)&Cl, g_Cl);

    const int projSmem = 8 * PSZ * (int)sizeof(bf16);     // 81920

    static bool attr_set = false;
    if (!attr_set) {
        cudaFuncSetAttribute(k_proj3, cudaFuncAttributeMaxDynamicSharedMemorySize, projSmem);
        cudaFuncSetAttribute(k_projo, cudaFuncAttributeMaxDynamicSharedMemorySize, projSmem);
        cudaFuncSetAttribute(k_att,  cudaFuncAttributeMaxDynamicSharedMemorySize, ATT_SMEM);
        attr_set = true;
    }

    // one batched conversion launch
    CvtArgs ca;
    ca.in[0] = tgt; ca.oh[0] = Th;  ca.ol[0] = Tl;  ca.n4[0] = BT * E_ / 4;
    ca.in[1] = src; ca.oh[1] = Sh;  ca.ol[1] = Sl;  ca.n4[1] = BT * E_ / 4;
    ca.in[2] = Wq;  ca.oh[2] = Wqh; ca.ol[2] = Wql; ca.n4[2] = E_ * E_ / 4;
    ca.in[3] = Wk;  ca.oh[3] = Wkh; ca.ol[3] = Wkl; ca.n4[3] = E_ * E_ / 4;
    ca.in[4] = Wv;  ca.oh[4] = Wvh; ca.ol[4] = Wvl; ca.n4[4] = E_ * E_ / 4;
    ca.in[5] = Wo;  ca.oh[5] = Woh; ca.ol[5] = Wol; ca.n4[5] = E_ * E_ / 4;
    k_cvt6<<<dim3((BT * E_ / 4 + 255) / 256, 1, 6), 256>>>(ca);

    k_proj3<<<dim3(E_ / 128, BT / 128, 3), dim3(256), projSmem>>>(
        Th, Tl, Sh, Sl, Wqh, Wql, Wkh, Wkl, Wvh, Wvl,
        Qh, Ql, Kh, Kl, Vh, Vl);

    k_att<<<dim3(T_ / 128, Z_), dim3(512), ATT_SMEM>>>(attn);

    k_projo<<<dim3(E_ / 128, BT / 128), dim3(256), projSmem>>>(Ch, Cl, Woh, Wol, out, bo);
}

// round 15
// speedup vs baseline: 1.0154x; 1.0154x over previous
#include <cuda_runtime.h>
#include <cuda_bf16.h>
#include <stdint.h>

#define B_  2
#define T_  2048
#define S_  2048
#define E_  1024
#define H_  16
#define D_  64
#define BT  (B_*T_)
#define Z_  (B_*H_)
#define SCALE 0.125f

typedef __nv_bfloat16 bf16;

// Scratch (__device__ globals; allocation-free rule)
__device__ bf16 g_Th[(size_t)BT*E_], g_Tl[(size_t)BT*E_];
__device__ bf16 g_Sh[(size_t)BT*E_], g_Sl[(size_t)BT*E_];
__device__ bf16 g_Wqh[(size_t)E_*E_], g_Wql[(size_t)E_*E_];
__device__ bf16 g_Wkh[(size_t)E_*E_], g_Wkl[(size_t)E_*E_];
__device__ bf16 g_Wvh[(size_t)E_*E_], g_Wvl[(size_t)E_*E_];
__device__ bf16 g_Woh[(size_t)E_*E_], g_Wol[(size_t)E_*E_];
__device__ bf16 g_Qh[(size_t)Z_*T_*D_], g_Ql[(size_t)Z_*T_*D_];
__device__ bf16 g_Kh[(size_t)Z_*S_*D_], g_Kl[(size_t)Z_*S_*D_];
__device__ bf16 g_Vh[(size_t)Z_*S_*D_], g_Vl[(size_t)Z_*S_*D_];
__device__ bf16 g_Ch[(size_t)BT*E_], g_Cl[(size_t)BT*E_];

__device__ __forceinline__ uint32_t smem_u32(const void* p) {
    return (uint32_t)__cvta_generic_to_shared(p);
}
__device__ __forceinline__ void cvt_hilo2(float x0, float x1, uint32_t& h, uint32_t& l) {
    asm("cvt.rn.bf16x2.f32 %0, %1, %2;" : "=r"(h) : "f"(x1), "f"(x0));
    float h0 = __uint_as_float(h << 16);
    float h1 = __uint_as_float(h & 0xffff0000u);
    asm("cvt.rn.bf16x2.f32 %0, %1, %2;" : "=r"(l) : "f"(x1 - h1), "f"(x0 - h0));
}
__device__ __forceinline__ void mma16816(float c[4], const uint32_t a[4], const uint32_t b[2]) {
    asm volatile("mma.sync.aligned.m16n8k16.row.col.f32.bf16.bf16.f32 "
        "{%0,%1,%2,%3}, {%4,%5,%6,%7}, {%8,%9}, {%0,%1,%2,%3};"
        : "+f"(c[0]), "+f"(c[1]), "+f"(c[2]), "+f"(c[3])
        : "r"(a[0]), "r"(a[1]), "r"(a[2]), "r"(a[3]), "r"(b[0]), "r"(b[1]));
}
__device__ __forceinline__ void ldsm4(uint32_t r[4], uint32_t a) {
    asm volatile("ldmatrix.sync.aligned.m8n8.x4.shared.b16 {%0,%1,%2,%3}, [%4];"
        : "=r"(r[0]), "=r"(r[1]), "=r"(r[2]), "=r"(r[3]) : "r"(a));
}
__device__ __forceinline__ void ldsm4t(uint32_t r[4], uint32_t a) {
    asm volatile("ldmatrix.sync.aligned.m8n8.x4.trans.shared.b16 {%0,%1,%2,%3}, [%4];"
        : "=r"(r[0]), "=r"(r[1]), "=r"(r[2]), "=r"(r[3]) : "r"(a));
}
__device__ __forceinline__ void cpa16p(const void* smem, const void* g) {
    asm volatile("cp.async.cg.shared.global [%0], [%1], 16;"
                 :: "r"(smem_u32(smem)), "l"(g));
}
__device__ __forceinline__ void cp_commit() { asm volatile("cp.async.commit_group;"); }
template<int N> __device__ __forceinline__ void cp_wait() {
    asm volatile("cp.async.wait_group %0;" :: "n"(N));
}
__device__ __forceinline__ float fast_exp_s(float x) {
    const float MAGIC = 12582912.0f;
    float t = x * (1.44269504088896f * SCALE);
    float r = t + MAGIC;
    int ib = __float_as_int(r);
    float f = t - (r - MAGIC);
    float p = 9.6181291e-3f;
    p = fmaf(p, f, 5.5504109e-2f);
    p = fmaf(p, f, 2.4022651e-1f);
    p = fmaf(p, f, 6.9314718e-1f);
    p = fmaf(p, f, 1.0f);
    return p * __int_as_float((ib + 127) << 23);
}

// ---------------------------------------------------------------------------
// Batched fp32 -> bf16 hi/lo converter
// ---------------------------------------------------------------------------
struct CvtArgs {
    const float* in[6];
    bf16* oh[6];
    bf16* ol[6];
    int n4[6];
};

__global__ void k_cvt6(CvtArgs a)
{
    const int z = blockIdx.z;
    int i = blockIdx.x * blockDim.x + threadIdx.x;
    if (i >= a.n4[z]) return;
    float4 v = ((const float4*)a.in[z])[i];
    uint32_t h01, l01, h23, l23;
    cvt_hilo2(v.x, v.y, h01, l01);
    cvt_hilo2(v.z, v.w, h23, l23);
    ((uint2*)a.oh[z])[i] = make_uint2(h01, h23);
    ((uint2*)a.ol[z])[i] = make_uint2(l01, l23);
}

// ---------------------------------------------------------------------------
// GEMM core (NT, 128x128x32, cp.async 2-stage, ldmatrix, bf16x3) — unchanged
// ---------------------------------------------------------------------------
#define PLD 40
#define PSZ (128*PLD)

template<bool TO_HL>
__device__ __forceinline__ void proj_core(
    const bf16* __restrict__ Agh, const bf16* __restrict__ Agl,
    const bf16* __restrict__ Bgh, const bf16* __restrict__ Bgl,
    float* __restrict__ C, const float* __restrict__ bias,
    bf16* __restrict__ Oh, bf16* __restrict__ Ol)
{
    extern __shared__ bf16 sm[];
    bf16* Ah = sm;
    bf16* Al = sm + 2 * PSZ;
    bf16* Bh = sm + 4 * PSZ;
    bf16* Bl = sm + 6 * PSZ;

    const int tid = threadIdx.x, lane = tid & 31, wid = tid >> 5;
    const int wm = wid >> 2, wn = wid & 3;
    const int bm = blockIdx.y * 128, bn = blockIdx.x * 128;
    const int rr = lane >> 2, q2 = (lane & 3) << 1;

    const int lrow = lane & 15, lkof = (lane >> 4) << 3;
    const int brow = ((lane >> 4) << 3) + (lane & 7);
    const int bkof = ((lane >> 3) & 1) << 3;

    auto issue = [&](int t, int buf) {
        const size_t k0 = (size_t)t * 32;
        #pragma unroll
        for (int i = 0; i < 2; i++) {
            int j = tid + i * 256;
            int r = j >> 2, c = (j & 3) << 3;
            size_t ga = (size_t)(bm + r) * E_ + k0 + c;
            size_t gb = (size_t)(bn + r) * E_ + k0 + c;
            int so = buf * PSZ + r * PLD + c;
            cpa16p(&Ah[so], &Agh[ga]);
            cpa16p(&Al[so], &Agl[ga]);
            cpa16p(&Bh[so], &Bgh[gb]);
            cpa16p(&Bl[so], &Bgl[gb]);
        }
        cp_commit();
    };

    float acc[4][4][4] = {};

    issue(0, 0);
    for (int t = 0; t < 32; t++) {
        const int buf = t & 1;
        if (t < 31) { issue(t + 1, buf ^ 1); cp_wait<1>(); }
        else cp_wait<0>();
        __syncthreads();

        const int bofs = buf * PSZ;
        uint32_t aAh[4], aAl[4];
        #pragma unroll
        for (int mt = 0; mt < 4; mt++) {
            int m = wm * 64 + mt * 16 + lrow;
            aAh[mt] = smem_u32(&Ah[bofs + m * PLD + lkof]);
            aAl[mt] = smem_u32(&Al[bofs + m * PLD + lkof]);
        }
        uint32_t aBh[2], aBl[2];
        #pragma unroll
        for (int ng = 0; ng < 2; ng++) {
            int n = wn * 32 + ng * 16 + brow;
            aBh[ng] = smem_u32(&Bh[bofs + n * PLD + bkof]);
            aBl[ng] = smem_u32(&Bl[bofs + n * PLD + bkof]);
        }

        #pragma unroll
        for (int ks = 0; ks < 2; ks++) {
            const uint32_t kb = ks * 32;
            uint32_t bh4[2][4], bl4[2][4];
            #pragma unroll
            for (int ng = 0; ng < 2; ng++) {
                ldsm4(bh4[ng], aBh[ng] + kb);
                ldsm4(bl4[ng], aBl[ng] + kb);
            }
            #pragma unroll
            for (int mt = 0; mt < 4; mt++) {
                uint32_t ah[4], al[4];
                ldsm4(ah, aAh[mt] + kb);
                ldsm4(al, aAl[mt] + kb);
                #pragma unroll
                for (int nt = 0; nt < 4; nt++) {
                    const int ng = nt >> 1, s = (nt & 1) << 1;
                    uint32_t bh[2] = { bh4[ng][s], bh4[ng][s + 1] };
                    uint32_t bl[2] = { bl4[ng][s], bl4[ng][s + 1] };
                    mma16816(acc[mt][nt], ah, bh);
                    mma16816(acc[mt][nt], al, bh);
                    mma16816(acc[mt][nt], ah, bl);
                }
            }
        }
        __syncthreads();
    }

    #pragma unroll
    for (int mt = 0; mt < 4; mt++) {
        #pragma unroll
        for (int nt = 0; nt < 4; nt++) {
            int n = bn + wn * 32 + nt * 8 + q2;
            #pragma unroll
            for (int rh = 0; rh < 2; rh++) {
                int m = bm + wm * 64 + mt * 16 + rr + rh * 8;
                float v0 = acc[mt][nt][rh * 2 + 0];
                float v1 = acc[mt][nt][rh * 2 + 1];
                if (TO_HL) {
                    int b = m >> 11, t = m & 2047;
                    int h = n >> 6, d = n & 63;
                    size_t off = ((size_t)(b * H_ + h) * T_ + t) * D_ + d;
                    uint32_t hh, ll;
                    cvt_hilo2(v0, v1, hh, ll);
                    *(uint32_t*)&Oh[off] = hh;
                    *(uint32_t*)&Ol[off] = ll;
                } else {
                    float* p = C + (size_t)m * E_ + n;
                    p[0] = v0 + bias[n];
                    p[1] = v1 + bias[n + 1];
                }
            }
        }
    }
}

__global__ __launch_bounds__(256, 2) void k_proj3(
    const bf16* __restrict__ Th, const bf16* __restrict__ Tl,
    const bf16* __restrict__ Sh, const bf16* __restrict__ Sl,
    const bf16* __restrict__ Wqh, const bf16* __restrict__ Wql,
    const bf16* __restrict__ Wkh, const bf16* __restrict__ Wkl,
    const bf16* __restrict__ Wvh, const bf16* __restrict__ Wvl,
    bf16* __restrict__ Qh, bf16* __restrict__ Ql,
    bf16* __restrict__ Kh, bf16* __restrict__ Kl,
    bf16* __restrict__ Vh, bf16* __restrict__ Vl)
{
    const int z = blockIdx.z;
    const bf16* Agh = (z == 0) ? Th : Sh;
    const bf16* Agl = (z == 0) ? Tl : Sl;
    const bf16* Bgh = (z == 0) ? Wqh : (z == 1) ? Wkh : Wvh;
    const bf16* Bgl = (z == 0) ? Wql : (z == 1) ? Wkl : Wvl;
    bf16* Oh = (z == 0) ? Qh : (z == 1) ? Kh : Vh;
    bf16* Ol = (z == 0) ? Ql : (z == 1) ? Kl : Vl;
    proj_core<true>(Agh, Agl, Bgh, Bgl, nullptr, nullptr, Oh, Ol);
}

__global__ __launch_bounds__(256, 2) void k_projo(
    const bf16* __restrict__ Agh, const bf16* __restrict__ Agl,
    const bf16* __restrict__ Bgh, const bf16* __restrict__ Bgl,
    float* __restrict__ C, const float* __restrict__ bias)
{
    proj_core<false>(Agh, Agl, Bgh, Bgl, C, bias, nullptr, nullptr);
}

// ---------------------------------------------------------------------------
// Fused attention, 512 threads (16 warps), DOUBLE-BUFFERED K/V (r13 pipeline).
// Warp tile: 16 t-rows x 64 s-cols.
// Pass 1: S=Qh*Kh (1 MMA), exp, row sums; Kh ring over 2 buffers.
// Pass 2: full bf16x3 S, p=e*inv_rs, write final attn once, PV from register
//         P-fragments; K/V 2-stage cp.async. 2-way ctx reduction via smem.
// ---------------------------------------------------------------------------
#define LDQ 72
#define QSZ (128*LDQ)
#define ATT_SMEM (10*QSZ*(int)sizeof(bf16))   // 184320

__global__ __launch_bounds__(512) void k_att(float* __restrict__ attn)
{
    extern __shared__ bf16 sm[];
    bf16* Qh = sm;
    bf16* Ql = sm + QSZ;
    bf16* Kh = sm + 2 * QSZ;      // [2][QSZ]
    bf16* Kl = sm + 4 * QSZ;      // [2][QSZ]
    bf16* Vh = sm + 6 * QSZ;      // [2][QSZ]
    bf16* Vl = sm + 8 * QSZ;      // [2][QSZ]
    __shared__ float rs[128];

    const int tid = threadIdx.x, lane = tid & 31, wid = tid >> 5;
    const int wm = wid >> 1, wn = wid & 1;           // 8 x 2 warps
    const int rr = lane >> 2, q2 = (lane & 3) << 1;
    const int z = blockIdx.y, t0 = blockIdx.x * 128;
    const int b = z >> 4, h = z & 15;

    const int lrow = lane & 15, lkof = (lane >> 4) << 3;
    const int brow = ((lane >> 4) << 3) + (lane & 7);
    const int bkof = ((lane >> 3) & 1) << 3;
    const int vkrow = ((lane >> 3) & 1) * 8 + (lane & 7);
    const int vncol = (lane >> 4) << 3;

    const bf16* Qhg = g_Qh + ((size_t)z * T_ + t0) * D_;
    const bf16* Qlg = g_Ql + ((size_t)z * T_ + t0) * D_;
    const bf16* Khg = g_Kh + (size_t)z * S_ * D_;
    const bf16* Klg = g_Kl + (size_t)z * S_ * D_;
    const bf16* Vhg = g_Vh + (size_t)z * S_ * D_;
    const bf16* Vlg = g_Vl + (size_t)z * S_ * D_;
    float* Ab = attn + (size_t)z * T_ * S_;

    if (tid < 128) rs[tid] = 0.f;

    #pragma unroll
    for (int i = 0; i < 2; i++) {
        int idx = tid + i * 512;
        int r = idx >> 3, c = (idx & 7) << 3;
        *(uint4*)&Qh[r * LDQ + c] = *(const uint4*)&Qhg[r * D_ + c];
        *(uint4*)&Ql[r * LDQ + c] = *(const uint4*)&Qlg[r * D_ + c];
    }

    // pass 1: Kh only, double-buffered within Kh[2]
    auto issueK1 = [&](int si, int buf) {
        const bf16* Kt = Khg + (size_t)si * 128 * D_;
        #pragma unroll
        for (int i = 0; i < 2; i++) {
            int j = tid + i * 512;
            int r = j >> 3, c = (j & 7) << 3;
            cpa16p(&Kh[buf * QSZ + r * LDQ + c], &Kt[r * D_ + c]);
        }
        cp_commit();
    };
    // pass 2: K hi/lo + V hi/lo, double-buffered
    auto issueKV = [&](int si, int buf) {
        const bf16* Kt = Khg + (size_t)si * 128 * D_;
        const bf16* Lt = Klg + (size_t)si * 128 * D_;
        const bf16* Vt = Vhg + (size_t)si * 128 * D_;
        const bf16* Wt = Vlg + (size_t)si * 128 * D_;
        #pragma unroll
        for (int i = 0; i < 2; i++) {
            int j = tid + i * 512;
            int r = j >> 3, c = (j & 7) << 3;
            cpa16p(&Kh[buf * QSZ + r * LDQ + c], &Kt[r * D_ + c]);
            cpa16p(&Kl[buf * QSZ + r * LDQ + c], &Lt[r * D_ + c]);
            cpa16p(&Vh[buf * QSZ + r * LDQ + c], &Vt[r * D_ + c]);
            cpa16p(&Vl[buf * QSZ + r * LDQ + c], &Wt[r * D_ + c]);
        }
        cp_commit();
    };

    const uint32_t aQh = smem_u32(&Qh[(wm * 16 + lrow) * LDQ + lkof]);
    const uint32_t aQl = smem_u32(&Ql[(wm * 16 + lrow) * LDQ + lkof]);

    // =================== PASS 1: row sums (1-MMA QK) ===================
    float psum[2] = {0.f, 0.f};
    issueK1(0, 0);
    for (int si = 0; si < 16; si++) {
        const int buf = si & 1;
        if (si < 15) { issueK1(si + 1, buf ^ 1); cp_wait<1>(); }
        else cp_wait<0>();
        __syncthreads();

        const bf16* base = Kh + buf * QSZ;
        uint32_t aKh[4];
        #pragma unroll
        for (int ng = 0; ng < 4; ng++) {
            int n = wn * 64 + ng * 16 + brow;
            aKh[ng] = smem_u32(&base[n * LDQ + bkof]);
        }

        float acc[8][4] = {};
        #pragma unroll
        for (int ks = 0; ks < 4; ks++) {
            const uint32_t kb = ks * 32;
            uint32_t ah[4];
            ldsm4(ah, aQh + kb);
            #pragma unroll
            for (int ng = 0; ng < 4; ng++) {
                uint32_t bh4[4];
                ldsm4(bh4, aKh[ng] + kb);
                #pragma unroll
                for (int s = 0; s < 2; s++) {
                    uint32_t bh[2] = { bh4[2 * s], bh4[2 * s + 1] };
                    mma16816(acc[ng * 2 + s], ah, bh);
                }
            }
        }

        #pragma unroll
        for (int nt = 0; nt < 8; nt++) {
            psum[0] += fast_exp_s(acc[nt][0]) + fast_exp_s(acc[nt][1]);
            psum[1] += fast_exp_s(acc[nt][2]) + fast_exp_s(acc[nt][3]);
        }
        __syncthreads();
    }

    atomicAdd(&rs[wm * 16 + rr], psum[0]);
    atomicAdd(&rs[wm * 16 + rr + 8], psum[1]);
    __syncthreads();
    if (tid < 128) rs[tid] = 1.0f / rs[tid];
    __syncthreads();

    // =================== PASS 2: attn write + PV (double-buffered) ========
    float ctx[8][4] = {};
    issueKV(0, 0);
    for (int si = 0; si < 16; si++) {
        const int buf = si & 1;
        if (si < 15) { issueKV(si + 1, buf ^ 1); cp_wait<1>(); }
        else cp_wait<0>();
        __syncthreads();

        const int kofs = buf * QSZ;
        uint32_t aKh[4], aKl[4];
        #pragma unroll
        for (int ng = 0; ng < 4; ng++) {
            int n = wn * 64 + ng * 16 + brow;
            aKh[ng] = smem_u32(&Kh[kofs + n * LDQ + bkof]);
            aKl[ng] = smem_u32(&Kl[kofs + n * LDQ + bkof]);
        }

        float acc[8][4] = {};
        #pragma unroll
        for (int ks = 0; ks < 4; ks++) {
            const uint32_t kb = ks * 32;
            uint32_t ah[4], al[4];
            ldsm4(ah, aQh + kb);
            ldsm4(al, aQl + kb);
            #pragma unroll
            for (int ng = 0; ng < 4; ng++) {
                uint32_t bh4[4], bl4[4];
                ldsm4(bh4, aKh[ng] + kb);
                ldsm4(bl4, aKl[ng] + kb);
                #pragma unroll
                for (int s = 0; s < 2; s++) {
                    const int nt = ng * 2 + s;
                    uint32_t bh[2] = { bh4[2 * s], bh4[2 * s + 1] };
                    uint32_t bl[2] = { bl4[2 * s], bl4[2 * s + 1] };
                    mma16816(acc[nt], ah, bh);
                    mma16816(acc[nt], al, bh);
                    mma16816(acc[nt], ah, bl);
                }
            }
        }

        // normalize + store final attn; keep p in acc
        {
            const int lr0 = wm * 16 + rr;
            const float inv0 = rs[lr0], inv1 = rs[lr0 + 8];
            const int r0 = t0 + lr0;
            #pragma unroll
            for (int nt = 0; nt < 8; nt++) {
                int n0 = si * 128 + wn * 64 + nt * 8 + q2;
                float p0 = fast_exp_s(acc[nt][0]) * inv0;
                float p1 = fast_exp_s(acc[nt][1]) * inv0;
                float p2 = fast_exp_s(acc[nt][2]) * inv1;
                float p3 = fast_exp_s(acc[nt][3]) * inv1;
                acc[nt][0] = p0; acc[nt][1] = p1;
                acc[nt][2] = p2; acc[nt][3] = p3;
                *(float2*)&Ab[(size_t)r0 * S_ + n0]       = make_float2(p0, p1);
                *(float2*)&Ab[(size_t)(r0 + 8) * S_ + n0] = make_float2(p2, p3);
            }
        }

        // PV: A-frags from register P (warp covers s-cols wn*64 + ks*16)
        const uint32_t vbase = smem_u32(Vh) + (uint32_t)(buf * QSZ * 2);
        const uint32_t lbase = smem_u32(Vl) + (uint32_t)(buf * QSZ * 2);
        #pragma unroll
        for (int ks = 0; ks < 4; ks++) {
            uint32_t pah[4], pal[4];
            cvt_hilo2(acc[2*ks][0],   acc[2*ks][1],   pah[0], pal[0]);
            cvt_hilo2(acc[2*ks][2],   acc[2*ks][3],   pah[1], pal[1]);
            cvt_hilo2(acc[2*ks+1][0], acc[2*ks+1][1], pah[2], pal[2]);
            cvt_hilo2(acc[2*ks+1][2], acc[2*ks+1][3], pah[3], pal[3]);
            const uint32_t srow = (uint32_t)(wn * 64 + ks * 16 + vkrow);
            #pragma unroll
            for (int ngd = 0; ngd < 4; ngd++) {
                const uint32_t voff = (srow * LDQ + ngd * 16 + vncol) * 2;
                uint32_t bh4[4], bl4[4];
                ldsm4t(bh4, vbase + voff);
                ldsm4t(bl4, lbase + voff);
                #pragma unroll
                for (int s = 0; s < 2; s++) {
                    const int ntd = ngd * 2 + s;
                    uint32_t bh[2] = { bh4[2 * s], bh4[2 * s + 1] };
                    uint32_t bl[2] = { bl4[2 * s], bl4[2 * s + 1] };
                    mma16816(ctx[ntd], pah, bh);
                    mma16816(ctx[ntd], pal, bh);
                    mma16816(ctx[ntd], pah, bl);
                }
            }
        }
        __syncthreads();
    }

    // ---- 2-way ctx reduction via smem atomics (red aliases K regions) ----
    float* red = (float*)Kh;             // 32KB needed; Kh[2] = 36KB
    #pragma unroll
    for (int i = 0; i < 16; i++) red[tid + i * 512] = 0.f;
    __syncthreads();
    {
        const int lr = wm * 16 + rr;
        #pragma unroll
        for (int ntd = 0; ntd < 8; ntd++) {
            int d = ntd * 8 + q2;
            atomicAdd(&red[lr * 64 + d],           ctx[ntd][0]);
            atomicAdd(&red[lr * 64 + d + 1],       ctx[ntd][1]);
            atomicAdd(&red[(lr + 8) * 64 + d],     ctx[ntd][2]);
            atomicAdd(&red[(lr + 8) * 64 + d + 1], ctx[ntd][3]);
        }
    }
    __syncthreads();
    #pragma unroll
    for (int i = 0; i < 8; i++) {
        int idx = tid + i * 512;         // 4096 bf16x2 pairs
        int r = idx >> 5, d2 = (idx & 31) << 1;
        float c0 = red[r * 64 + d2], c1 = red[r * 64 + d2 + 1];
        uint32_t hh, ll;
        cvt_hilo2(c0, c1, hh, ll);
        size_t off = ((size_t)(b * T_ + t0 + r)) * E_ + h * D_ + d2;
        *(uint32_t*)&g_Ch[off] = hh;
        *(uint32_t*)&g_Cl[off] = ll;
    }
}

// ---------------------------------------------------------------------------
extern "C" void kernel_launch(void* const* d_in, const int* in_sizes, int n_in,
                              void* d_out, int out_size)
{
    const float* src = (const float*)d_in[0];
    const float* tgt = (const float*)d_in[1];
    const float* Wq  = (const float*)d_in[2];
    const float* Wk  = (const float*)d_in[3];
    const float* Wv  = (const float*)d_in[4];
    const float* Wo  = (const float*)d_in[5];
    const float* bo  = (const float*)d_in[6];

    float* out  = (float*)d_out;
    float* attn = out + (size_t)BT * E_;

    bf16 *Th, *Tl, *Sh, *Sl, *Wqh, *Wql, *Wkh, *Wkl, *Wvh, *Wvl, *Woh, *Wol;
    bf16 *Qh, *Ql, *Kh, *Kl, *Vh, *Vl, *Ch, *Cl;
    cudaGetSymbolAddress((void**)&Th, g_Th);   cudaGetSymbolAddress((void**)&Tl, g_Tl);
    cudaGetSymbolAddress((void**)&Sh, g_Sh);   cudaGetSymbolAddress((void**)&Sl, g_Sl);
    cudaGetSymbolAddress((void**)&Wqh, g_Wqh); cudaGetSymbolAddress((void**)&Wql, g_Wql);
    cudaGetSymbolAddress((void**)&Wkh, g_Wkh); cudaGetSymbolAddress((void**)&Wkl, g_Wkl);
    cudaGetSymbolAddress((void**)&Wvh, g_Wvh); cudaGetSymbolAddress((void**)&Wvl, g_Wvl);
    cudaGetSymbolAddress((void**)&Woh, g_Woh); cudaGetSymbolAddress((void**)&Wol, g_Wol);
    cudaGetSymbolAddress((void**)&Qh, g_Qh);   cudaGetSymbolAddress((void**)&Ql, g_Ql);
    cudaGetSymbolAddress((void**)&Kh, g_Kh);   cudaGetSymbolAddress((void**)&Kl, g_Kl);
    cudaGetSymbolAddress((void**)&Vh, g_Vh);   cudaGetSymbolAddress((void**)&Vl, g_Vl);
    cudaGetSymbolAddress((void**)&Ch, g_Ch);   cudaGetSymbolAddress((void**)&Cl, g_Cl);

    const int projSmem = 8 * PSZ * (int)sizeof(bf16);     // 81920

    static bool attr_set = false;
    if (!attr_set) {
        cudaFuncSetAttribute(k_proj3, cudaFuncAttributeMaxDynamicSharedMemorySize, projSmem);
        cudaFuncSetAttribute(k_projo, cudaFuncAttributeMaxDynamicSharedMemorySize, projSmem);
        cudaFuncSetAttribute(k_att,  cudaFuncAttributeMaxDynamicSharedMemorySize, ATT_SMEM);
        attr_set = true;
    }

    // one batched conversion launch
    CvtArgs ca;
    ca.in[0] = tgt; ca.oh[0] = Th;  ca.ol[0] = Tl;  ca.n4[0] = BT * E_ / 4;
    ca.in[1] = src; ca.oh[1] = Sh;  ca.ol[1] = Sl;  ca.n4[1] = BT * E_ / 4;
    ca.in[2] = Wq;  ca.oh[2] = Wqh; ca.ol[2] = Wql; ca.n4[2] = E_ * E_ / 4;
    ca.in[3] = Wk;  ca.oh[3] = Wkh; ca.ol[3] = Wkl; ca.n4[3] = E_ * E_ / 4;
    ca.in[4] = Wv;  ca.oh[4] = Wvh; ca.ol[4] = Wvl; ca.n4[4] = E_ * E_ / 4;
    ca.in[5] = Wo;  ca.oh[5] = Woh; ca.ol[5] = Wol; ca.n4[5] = E_ * E_ / 4;
    k_cvt6<<<dim3((BT * E_ / 4 + 255) / 256, 1, 6), 256>>>(ca);

    k_proj3<<<dim3(E_ / 128, BT / 128, 3), dim3(256), projSmem>>>(
        Th, Tl, Sh, Sl, Wqh, Wql, Wkh, Wkl, Wvh, Wvl,
        Qh, Ql, Kh, Kl, Vh, Vl);

    k_att<<<dim3(T_ / 128, Z_), dim3(512), ATT_SMEM>>>(attn);

    k_projo<<<dim3(E_ / 128, BT / 128), dim3(256), projSmem>>>(Ch, Cl, Woh, Wol, out, bo);
}

// round 17
// speedup vs baseline: 1.0786x; 1.0623x over previous
#include <cuda_runtime.h>
#include <cuda_bf16.h>
#include <stdint.h>

#define B_  2
#define T_  2048
#define S_  2048
#define E_  1024
#define H_  16
#define D_  64
#define BT  (B_*T_)
#define Z_  (B_*H_)
#define SCALE 0.125f

typedef __nv_bfloat16 bf16;

// Scratch (__device__ globals; allocation-free rule)
__device__ bf16 g_Th[(size_t)BT*E_], g_Tl[(size_t)BT*E_];
__device__ bf16 g_Sh[(size_t)BT*E_], g_Sl[(size_t)BT*E_];
__device__ bf16 g_Wqh[(size_t)E_*E_], g_Wql[(size_t)E_*E_];
__device__ bf16 g_Wkh[(size_t)E_*E_], g_Wkl[(size_t)E_*E_];
__device__ bf16 g_Wvh[(size_t)E_*E_], g_Wvl[(size_t)E_*E_];
__device__ bf16 g_Woh[(size_t)E_*E_], g_Wol[(size_t)E_*E_];
__device__ bf16 g_Qh[(size_t)Z_*T_*D_], g_Ql[(size_t)Z_*T_*D_];
__device__ bf16 g_Kh[(size_t)Z_*S_*D_], g_Kl[(size_t)Z_*S_*D_];
__device__ bf16 g_Vh[(size_t)Z_*S_*D_], g_Vl[(size_t)Z_*S_*D_];
__device__ bf16 g_Ch[(size_t)BT*E_], g_Cl[(size_t)BT*E_];

__device__ __forceinline__ uint32_t smem_u32(const void* p) {
    return (uint32_t)__cvta_generic_to_shared(p);
}
__device__ __forceinline__ void cvt_hilo2(float x0, float x1, uint32_t& h, uint32_t& l) {
    asm("cvt.rn.bf16x2.f32 %0, %1, %2;" : "=r"(h) : "f"(x1), "f"(x0));
    float h0 = __uint_as_float(h << 16);
    float h1 = __uint_as_float(h & 0xffff0000u);
    asm("cvt.rn.bf16x2.f32 %0, %1, %2;" : "=r"(l) : "f"(x1 - h1), "f"(x0 - h0));
}
__device__ __forceinline__ void mma16816(float c[4], const uint32_t a[4], const uint32_t b[2]) {
    asm volatile("mma.sync.aligned.m16n8k16.row.col.f32.bf16.bf16.f32 "
        "{%0,%1,%2,%3}, {%4,%5,%6,%7}, {%8,%9}, {%0,%1,%2,%3};"
        : "+f"(c[0]), "+f"(c[1]), "+f"(c[2]), "+f"(c[3])
        : "r"(a[0]), "r"(a[1]), "r"(a[2]), "r"(a[3]), "r"(b[0]), "r"(b[1]));
}
__device__ __forceinline__ void ldsm4(uint32_t r[4], uint32_t a) {
    asm volatile("ldmatrix.sync.aligned.m8n8.x4.shared.b16 {%0,%1,%2,%3}, [%4];"
        : "=r"(r[0]), "=r"(r[1]), "=r"(r[2]), "=r"(r[3]) : "r"(a));
}
__device__ __forceinline__ void ldsm4t(uint32_t r[4], uint32_t a) {
    asm volatile("ldmatrix.sync.aligned.m8n8.x4.trans.shared.b16 {%0,%1,%2,%3}, [%4];"
        : "=r"(r[0]), "=r"(r[1]), "=r"(r[2]), "=r"(r[3]) : "r"(a));
}
__device__ __forceinline__ void cpa16p(const void* smem, const void* g) {
    asm volatile("cp.async.cg.shared.global [%0], [%1], 16;"
                 :: "r"(smem_u32(smem)), "l"(g));
}
__device__ __forceinline__ void cp_commit() { asm volatile("cp.async.commit_group;"); }
template<int N> __device__ __forceinline__ void cp_wait() {
    asm volatile("cp.async.wait_group %0;" :: "n"(N));
}
__device__ __forceinline__ float fast_exp_s(float x) {
    const float MAGIC = 12582912.0f;
    float t = x * (1.44269504088896f * SCALE);
    float r = t + MAGIC;
    int ib = __float_as_int(r);
    float f = t - (r - MAGIC);
    float p = 9.6181291e-3f;
    p = fmaf(p, f, 5.5504109e-2f);
    p = fmaf(p, f, 2.4022651e-1f);
    p = fmaf(p, f, 6.9314718e-1f);
    p = fmaf(p, f, 1.0f);
    return p * __int_as_float((ib + 127) << 23);
}

// ---------------------------------------------------------------------------
// Batched fp32 -> bf16 hi/lo converter
// ---------------------------------------------------------------------------
struct CvtArgs {
    const float* in[6];
    bf16* oh[6];
    bf16* ol[6];
    int n4[6];
};

__global__ void k_cvt6(CvtArgs a)
{
    const int z = blockIdx.z;
    int i = blockIdx.x * blockDim.x + threadIdx.x;
    if (i >= a.n4[z]) return;
    float4 v = ((const float4*)a.in[z])[i];
    uint32_t h01, l01, h23, l23;
    cvt_hilo2(v.x, v.y, h01, l01);
    cvt_hilo2(v.z, v.w, h23, l23);
    ((uint2*)a.oh[z])[i] = make_uint2(h01, h23);
    ((uint2*)a.ol[z])[i] = make_uint2(l01, l23);
}

// ---------------------------------------------------------------------------
// GEMM core (NT, 128x128x32, cp.async 2-stage, ldmatrix, bf16x3)
// ---------------------------------------------------------------------------
#define PLD 40
#define PSZ (128*PLD)

template<bool TO_HL>
__device__ __forceinline__ void proj_core(
    const bf16* __restrict__ Agh, const bf16* __restrict__ Agl,
    const bf16* __restrict__ Bgh, const bf16* __restrict__ Bgl,
    float* __restrict__ C, const float* __restrict__ bias,
    bf16* __restrict__ Oh, bf16* __restrict__ Ol)
{
    extern __shared__ bf16 sm[];
    bf16* Ah = sm;
    bf16* Al = sm + 2 * PSZ;
    bf16* Bh = sm + 4 * PSZ;
    bf16* Bl = sm + 6 * PSZ;

    const int tid = threadIdx.x, lane = tid & 31, wid = tid >> 5;
    const int wm = wid >> 2, wn = wid & 3;
    const int bm = blockIdx.y * 128, bn = blockIdx.x * 128;
    const int rr = lane >> 2, q2 = (lane & 3) << 1;

    const int lrow = lane & 15, lkof = (lane >> 4) << 3;
    const int brow = ((lane >> 4) << 3) + (lane & 7);
    const int bkof = ((lane >> 3) & 1) << 3;

    auto issue = [&](int t, int buf) {
        const size_t k0 = (size_t)t * 32;
        #pragma unroll
        for (int i = 0; i < 2; i++) {
            int j = tid + i * 256;
            int r = j >> 2, c = (j & 3) << 3;
            size_t ga = (size_t)(bm + r) * E_ + k0 + c;
            size_t gb = (size_t)(bn + r) * E_ + k0 + c;
            int so = buf * PSZ + r * PLD + c;
            cpa16p(&Ah[so], &Agh[ga]);
            cpa16p(&Al[so], &Agl[ga]);
            cpa16p(&Bh[so], &Bgh[gb]);
            cpa16p(&Bl[so], &Bgl[gb]);
        }
        cp_commit();
    };

    float acc[4][4][4] = {};

    issue(0, 0);
    for (int t = 0; t < 32; t++) {
        const int buf = t & 1;
        if (t < 31) { issue(t + 1, buf ^ 1); cp_wait<1>(); }
        else cp_wait<0>();
        __syncthreads();

        const int bofs = buf * PSZ;
        uint32_t aAh[4], aAl[4];
        #pragma unroll
        for (int mt = 0; mt < 4; mt++) {
            int m = wm * 64 + mt * 16 + lrow;
            aAh[mt] = smem_u32(&Ah[bofs + m * PLD + lkof]);
            aAl[mt] = smem_u32(&Al[bofs + m * PLD + lkof]);
        }
        uint32_t aBh[2], aBl[2];
        #pragma unroll
        for (int ng = 0; ng < 2; ng++) {
            int n = wn * 32 + ng * 16 + brow;
            aBh[ng] = smem_u32(&Bh[bofs + n * PLD + bkof]);
            aBl[ng] = smem_u32(&Bl[bofs + n * PLD + bkof]);
        }

        #pragma unroll
        for (int ks = 0; ks < 2; ks++) {
            const uint32_t kb = ks * 32;
            uint32_t bh4[2][4], bl4[2][4];
            #pragma unroll
            for (int ng = 0; ng < 2; ng++) {
                ldsm4(bh4[ng], aBh[ng] + kb);
                ldsm4(bl4[ng], aBl[ng] + kb);
            }
            #pragma unroll
            for (int mt = 0; mt < 4; mt++) {
                uint32_t ah[4], al[4];
                ldsm4(ah, aAh[mt] + kb);
                ldsm4(al, aAl[mt] + kb);
                #pragma unroll
                for (int nt = 0; nt < 4; nt++) {
                    const int ng = nt >> 1, s = (nt & 1) << 1;
                    uint32_t bh[2] = { bh4[ng][s], bh4[ng][s + 1] };
                    uint32_t bl[2] = { bl4[ng][s], bl4[ng][s + 1] };
                    mma16816(acc[mt][nt], ah, bh);
                    mma16816(acc[mt][nt], al, bh);
                    mma16816(acc[mt][nt], ah, bl);
                }
            }
        }
        __syncthreads();
    }

    #pragma unroll
    for (int mt = 0; mt < 4; mt++) {
        #pragma unroll
        for (int nt = 0; nt < 4; nt++) {
            int n = bn + wn * 32 + nt * 8 + q2;
            #pragma unroll
            for (int rh = 0; rh < 2; rh++) {
                int m = bm + wm * 64 + mt * 16 + rr + rh * 8;
                float v0 = acc[mt][nt][rh * 2 + 0];
                float v1 = acc[mt][nt][rh * 2 + 1];
                if (TO_HL) {
                    int b = m >> 11, t = m & 2047;
                    int h = n >> 6, d = n & 63;
                    size_t off = ((size_t)(b * H_ + h) * T_ + t) * D_ + d;
                    uint32_t hh, ll;
                    cvt_hilo2(v0, v1, hh, ll);
                    *(uint32_t*)&Oh[off] = hh;
                    *(uint32_t*)&Ol[off] = ll;
                } else {
                    float* p = C + (size_t)m * E_ + n;
                    p[0] = v0 + bias[n];
                    p[1] = v1 + bias[n + 1];
                }
            }
        }
    }
}

__global__ __launch_bounds__(256, 2) void k_proj3(
    const bf16* __restrict__ Th, const bf16* __restrict__ Tl,
    const bf16* __restrict__ Sh, const bf16* __restrict__ Sl,
    const bf16* __restrict__ Wqh, const bf16* __restrict__ Wql,
    const bf16* __restrict__ Wkh, const bf16* __restrict__ Wkl,
    const bf16* __restrict__ Wvh, const bf16* __restrict__ Wvl,
    bf16* __restrict__ Qh, bf16* __restrict__ Ql,
    bf16* __restrict__ Kh, bf16* __restrict__ Kl,
    bf16* __restrict__ Vh, bf16* __restrict__ Vl)
{
    const int z = blockIdx.z;
    const bf16* Agh = (z == 0) ? Th : Sh;
    const bf16* Agl = (z == 0) ? Tl : Sl;
    const bf16* Bgh = (z == 0) ? Wqh : (z == 1) ? Wkh : Wvh;
    const bf16* Bgl = (z == 0) ? Wql : (z == 1) ? Wkl : Wvl;
    bf16* Oh = (z == 0) ? Qh : (z == 1) ? Kh : Vh;
    bf16* Ol = (z == 0) ? Ql : (z == 1) ? Kl : Vl;
    proj_core<true>(Agh, Agl, Bgh, Bgl, nullptr, nullptr, Oh, Ol);
}

__global__ __launch_bounds__(256, 2) void k_projo(
    const bf16* __restrict__ Agh, const bf16* __restrict__ Agl,
    const bf16* __restrict__ Bgh, const bf16* __restrict__ Bgl,
    float* __restrict__ C, const float* __restrict__ bias)
{
    proj_core<false>(Agh, Agl, Bgh, Bgl, C, bias, nullptr, nullptr);
}

// ---------------------------------------------------------------------------
// Fused attention (r13 structure: 256 threads, 8 warps, double-buffered KV).
// Pass 1: S=Qh*Kh (1 MMA), exp, row sums (no stores).
// Pass 2: full bf16x3 S, p=e*inv_rs, write FINAL attn once, PV from register
//         P-fragments; 2-way ctx reduction via smem.
// ---------------------------------------------------------------------------
#define LDQ 72
#define QSZ (128*LDQ)

__global__ __launch_bounds__(256) void k_att(float* __restrict__ attn)
{
    extern __shared__ bf16 sm[];
    bf16* Qh = sm;
    bf16* Ql = sm + QSZ;
    bf16* Kh = sm + 2 * QSZ;      // [2][QSZ]
    bf16* Kl = sm + 4 * QSZ;      // [2][QSZ] (pass 2 only)
    bf16* Vh = sm + 6 * QSZ;      // [2][QSZ]
    bf16* Vl = sm + 8 * QSZ;
    __shared__ float rs[128];

    const int tid = threadIdx.x, lane = tid & 31, wid = tid >> 5;
    const int wm = wid >> 1, wn = wid & 1;
    const int rr = lane >> 2, q2 = (lane & 3) << 1;
    const int z = blockIdx.y, t0 = blockIdx.x * 128;
    const int b = z >> 4, h = z & 15;

    const int lrow = lane & 15, lkof = (lane >> 4) << 3;
    const int brow = ((lane >> 4) << 3) + (lane & 7);
    const int bkof = ((lane >> 3) & 1) << 3;
    const int vkrow = ((lane >> 3) & 1) * 8 + (lane & 7);
    const int vncol = (lane >> 4) << 3;

    const bf16* Qhg = g_Qh + ((size_t)z * T_ + t0) * D_;
    const bf16* Qlg = g_Ql + ((size_t)z * T_ + t0) * D_;
    const bf16* Khg = g_Kh + (size_t)z * S_ * D_;
    const bf16* Klg = g_Kl + (size_t)z * S_ * D_;
    const bf16* Vhg = g_Vh + (size_t)z * S_ * D_;
    const bf16* Vlg = g_Vl + (size_t)z * S_ * D_;
    float* Ab = attn + (size_t)z * T_ * S_;

    if (tid < 128) rs[tid] = 0.f;

    #pragma unroll
    for (int i = 0; i < 4; i++) {
        int idx = tid + i * 256;
        int r = idx >> 3, c = (idx & 7) << 3;
        *(uint4*)&Qh[r * LDQ + c] = *(const uint4*)&Qhg[r * D_ + c];
        *(uint4*)&Ql[r * LDQ + c] = *(const uint4*)&Qlg[r * D_ + c];
    }

    // pass 1: K-hi only
    auto issueK1 = [&](int si, int buf) {
        const bf16* Kt = Khg + (size_t)si * 128 * D_;
        #pragma unroll
        for (int i = 0; i < 4; i++) {
            int j = tid + i * 256;
            int r = j >> 3, c = (j & 7) << 3;
            cpa16p(&Kh[buf * QSZ + r * LDQ + c], &Kt[r * D_ + c]);
        }
        cp_commit();
    };
    auto issueKV = [&](int si, int buf) {
        const bf16* Kt = Khg + (size_t)si * 128 * D_;
        const bf16* Lt = Klg + (size_t)si * 128 * D_;
        const bf16* Vt = Vhg + (size_t)si * 128 * D_;
        const bf16* Wt = Vlg + (size_t)si * 128 * D_;
        #pragma unroll
        for (int i = 0; i < 4; i++) {
            int j = tid + i * 256;
            int r = j >> 3, c = (j & 7) << 3;
            cpa16p(&Kh[buf * QSZ + r * LDQ + c], &Kt[r * D_ + c]);
            cpa16p(&Kl[buf * QSZ + r * LDQ + c], &Lt[r * D_ + c]);
            cpa16p(&Vh[buf * QSZ + r * LDQ + c], &Vt[r * D_ + c]);
            cpa16p(&Vl[buf * QSZ + r * LDQ + c], &Wt[r * D_ + c]);
        }
        cp_commit();
    };

    uint32_t aQh[2], aQl[2];
    #pragma unroll
    for (int mt = 0; mt < 2; mt++) {
        int m = wm * 32 + mt * 16 + lrow;
        aQh[mt] = smem_u32(&Qh[m * LDQ + lkof]);
        aQl[mt] = smem_u32(&Ql[m * LDQ + lkof]);
    }

    // =================== PASS 1: row sums (1-MMA QK) ===================
    float psum[2][2] = {};
    issueK1(0, 0);
    for (int si = 0; si < 16; si++) {
        const int buf = si & 1;
        if (si < 15) { issueK1(si + 1, buf ^ 1); cp_wait<1>(); }
        else cp_wait<0>();
        __syncthreads();

        const int kofs = buf * QSZ;
        uint32_t aKh[4];
        #pragma unroll
        for (int ng = 0; ng < 4; ng++) {
            int n = wn * 64 + ng * 16 + brow;
            aKh[ng] = smem_u32(&Kh[kofs + n * LDQ + bkof]);
        }

        float acc[2][8][4] = {};
        #pragma unroll
        for (int ks = 0; ks < 4; ks++) {
            const uint32_t kb = ks * 32;
            uint32_t ah[2][4];
            #pragma unroll
            for (int mt = 0; mt < 2; mt++) {
                ldsm4(ah[mt], aQh[mt] + kb);
            }
            #pragma unroll
            for (int ng = 0; ng < 4; ng++) {
                uint32_t bh4[4];
                ldsm4(bh4, aKh[ng] + kb);
                #pragma unroll
                for (int s = 0; s < 2; s++) {
                    const int nt = ng * 2 + s;
                    uint32_t bh[2] = { bh4[2 * s], bh4[2 * s + 1] };
                    #pragma unroll
                    for (int mt = 0; mt < 2; mt++) {
                        mma16816(acc[mt][nt], ah[mt], bh);
                    }
                }
            }
        }

        #pragma unroll
        for (int mt = 0; mt < 2; mt++) {
            #pragma unroll
            for (int nt = 0; nt < 8; nt++) {
                psum[mt][0] += fast_exp_s(acc[mt][nt][0]) + fast_exp_s(acc[mt][nt][1]);
                psum[mt][1] += fast_exp_s(acc[mt][nt][2]) + fast_exp_s(acc[mt][nt][3]);
            }
        }
        __syncthreads();
    }

    #pragma unroll
    for (int mt = 0; mt < 2; mt++) {
        atomicAdd(&rs[wm * 32 + mt * 16 + rr], psum[mt][0]);
        atomicAdd(&rs[wm * 32 + mt * 16 + rr + 8], psum[mt][1]);
    }
    __syncthreads();
    if (tid < 128) rs[tid] = 1.0f / rs[tid];
    __syncthreads();

    // =================== PASS 2: attn write + PV ===================
    float ctx[2][8][4] = {};
    issueKV(0, 0);
    for (int si = 0; si < 16; si++) {
        const int buf = si & 1;
        if (si < 15) { issueKV(si + 1, buf ^ 1); cp_wait<1>(); }
        else cp_wait<0>();
        __syncthreads();

        const int kofs = buf * QSZ;
        uint32_t aKh[4], aKl[4];
        #pragma unroll
        for (int ng = 0; ng < 4; ng++) {
            int n = wn * 64 + ng * 16 + brow;
            aKh[ng] = smem_u32(&Kh[kofs + n * LDQ + bkof]);
            aKl[ng] = smem_u32(&Kl[kofs + n * LDQ + bkof]);
        }

        float acc[2][8][4] = {};
        #pragma unroll
        for (int ks = 0; ks < 4; ks++) {
            const uint32_t kb = ks * 32;
            uint32_t ah[2][4], al[2][4];
            #pragma unroll
            for (int mt = 0; mt < 2; mt++) {
                ldsm4(ah[mt], aQh[mt] + kb);
                ldsm4(al[mt], aQl[mt] + kb);
            }
            #pragma unroll
            for (int ng = 0; ng < 4; ng++) {
                uint32_t bh4[4], bl4[4];
                ldsm4(bh4, aKh[ng] + kb);
                ldsm4(bl4, aKl[ng] + kb);
                #pragma unroll
                for (int s = 0; s < 2; s++) {
                    const int nt = ng * 2 + s;
                    uint32_t bh[2] = { bh4[2 * s], bh4[2 * s + 1] };
                    uint32_t bl[2] = { bl4[2 * s], bl4[2 * s + 1] };
                    #pragma unroll
                    for (int mt = 0; mt < 2; mt++) {
                        mma16816(acc[mt][nt], ah[mt], bh);
                        mma16816(acc[mt][nt], al[mt], bh);
                        mma16816(acc[mt][nt], ah[mt], bl);
                    }
                }
            }
        }

        // normalize + store final attn; keep p in acc for PV fragments
        #pragma unroll
        for (int mt = 0; mt < 2; mt++) {
            const int lr0 = wm * 32 + mt * 16 + rr;
            const float inv0 = rs[lr0], inv1 = rs[lr0 + 8];
            const int r0 = t0 + lr0;
            #pragma unroll
            for (int nt = 0; nt < 8; nt++) {
                int n0 = si * 128 + wn * 64 + nt * 8 + q2;
                float p0 = fast_exp_s(acc[mt][nt][0]) * inv0;
                float p1 = fast_exp_s(acc[mt][nt][1]) * inv0;
                float p2 = fast_exp_s(acc[mt][nt][2]) * inv1;
                float p3 = fast_exp_s(acc[mt][nt][3]) * inv1;
                acc[mt][nt][0] = p0; acc[mt][nt][1] = p1;
                acc[mt][nt][2] = p2; acc[mt][nt][3] = p3;
                *(float2*)&Ab[(size_t)r0 * S_ + n0]       = make_float2(p0, p1);
                *(float2*)&Ab[(size_t)(r0 + 8) * S_ + n0] = make_float2(p2, p3);
            }
        }

        // PV: A-frags from register P (warp covers s-cols wn*64 + ks*16)
        const uint32_t vbase = smem_u32(&Vh[buf * QSZ]);
        const uint32_t lbase = smem_u32(&Vl[buf * QSZ]);
        #pragma unroll
        for (int ks = 0; ks < 4; ks++) {
            uint32_t pah[2][4], pal[2][4];
            #pragma unroll
            for (int mt = 0; mt < 2; mt++) {
                cvt_hilo2(acc[mt][2*ks][0],   acc[mt][2*ks][1],   pah[mt][0], pal[mt][0]);
                cvt_hilo2(acc[mt][2*ks][2],   acc[mt][2*ks][3],   pah[mt][1], pal[mt][1]);
                cvt_hilo2(acc[mt][2*ks+1][0], acc[mt][2*ks+1][1], pah[mt][2], pal[mt][2]);
                cvt_hilo2(acc[mt][2*ks+1][2], acc[mt][2*ks+1][3], pah[mt][3], pal[mt][3]);
            }
            const uint32_t srow = (uint32_t)(wn * 64 + ks * 16 + vkrow);
            #pragma unroll
            for (int ngd = 0; ngd < 4; ngd++) {
                const uint32_t voff = (srow * LDQ + ngd * 16 + vncol) * 2;
                uint32_t bh4[4], bl4[4];
                ldsm4t(bh4, vbase + voff);
                ldsm4t(bl4, lbase + voff);
                #pragma unroll
                for (int s = 0; s < 2; s++) {
                    const int ntd = ngd * 2 + s;
                    uint32_t bh[2] = { bh4[2 * s], bh4[2 * s + 1] };
                    uint32_t bl[2] = { bl4[2 * s], bl4[2 * s + 1] };
                    #pragma unroll
                    for (int mt = 0; mt < 2; mt++) {
                        mma16816(ctx[mt][ntd], pah[mt], bh);
                        mma16816(ctx[mt][ntd], pal[mt], bh);
                        mma16816(ctx[mt][ntd], pah[mt], bl);
                    }
                }
            }
        }
        __syncthreads();
    }

    // ---- cross-wn reduction of ctx partials via smem, then write hi/lo ----
    float* red = (float*)Vh;   // 32KB needed, Vh region is 36KB
    if (wn == 1) {
        #pragma unroll
        for (int mt = 0; mt < 2; mt++) {
            #pragma unroll
            for (int ntd = 0; ntd < 8; ntd++) {
                int d = ntd * 8 + q2;
                int lr = wm * 32 + mt * 16 + rr;
                *(float2*)&red[lr * 64 + d]       = make_float2(ctx[mt][ntd][0], ctx[mt][ntd][1]);
                *(float2*)&red[(lr + 8) * 64 + d] = make_float2(ctx[mt][ntd][2], ctx[mt][ntd][3]);
            }
        }
    }
    __syncthreads();
    if (wn == 0) {
        #pragma unroll
        for (int mt = 0; mt < 2; mt++) {
            #pragma unroll
            for (int ntd = 0; ntd < 8; ntd++) {
                int d = ntd * 8 + q2;
                int lr = wm * 32 + mt * 16 + rr;
                float2 o0 = *(float2*)&red[lr * 64 + d];
                float2 o1 = *(float2*)&red[(lr + 8) * 64 + d];
                float c0 = ctx[mt][ntd][0] + o0.x;
                float c1 = ctx[mt][ntd][1] + o0.y;
                float c2 = ctx[mt][ntd][2] + o1.x;
                float c3 = ctx[mt][ntd][3] + o1.y;
                uint32_t hh, ll;
                size_t off0 = ((size_t)(b * T_ + t0 + lr)) * E_ + h * D_ + d;
                cvt_hilo2(c0, c1, hh, ll);
                *(uint32_t*)&g_Ch[off0] = hh;
                *(uint32_t*)&g_Cl[off0] = ll;
                size_t off1 = off0 + (size_t)8 * E_;
                cvt_hilo2(c2, c3, hh, ll);
                *(uint32_t*)&g_Ch[off1] = hh;
                *(uint32_t*)&g_Cl[off1] = ll;
            }
        }
    }
}

// ---------------------------------------------------------------------------
extern "C" void kernel_launch(void* const* d_in, const int* in_sizes, int n_in,
                              void* d_out, int out_size)
{
    const float* src = (const float*)d_in[0];
    const float* tgt = (const float*)d_in[1];
    const float* Wq  = (const float*)d_in[2];
    const float* Wk  = (const float*)d_in[3];
    const float* Wv  = (const float*)d_in[4];
    const float* Wo  = (const float*)d_in[5];
    const float* bo  = (const float*)d_in[6];

    float* out  = (float*)d_out;
    float* attn = out + (size_t)BT * E_;

    bf16 *Th, *Tl, *Sh, *Sl, *Wqh, *Wql, *Wkh, *Wkl, *Wvh, *Wvl, *Woh, *Wol;
    bf16 *Qh, *Ql, *Kh, *Kl, *Vh, *Vl, *Ch, *Cl;
    cudaGetSymbolAddress((void**)&Th, g_Th);   cudaGetSymbolAddress((void**)&Tl, g_Tl);
    cudaGetSymbolAddress((void**)&Sh, g_Sh);   cudaGetSymbolAddress((void**)&Sl, g_Sl);
    cudaGetSymbolAddress((void**)&Wqh, g_Wqh); cudaGetSymbolAddress((void**)&Wql, g_Wql);
    cudaGetSymbolAddress((void**)&Wkh, g_Wkh); cudaGetSymbolAddress((void**)&Wkl, g_Wkl);
    cudaGetSymbolAddress((void**)&Wvh, g_Wvh); cudaGetSymbolAddress((void**)&Wvl, g_Wvl);
    cudaGetSymbolAddress((void**)&Woh, g_Woh); cudaGetSymbolAddress((void**)&Wol, g_Wol);
    cudaGetSymbolAddress((void**)&Qh, g_Qh);   cudaGetSymbolAddress((void**)&Ql, g_Ql);
    cudaGetSymbolAddress((void**)&Kh, g_Kh);   cudaGetSymbolAddress((void**)&Kl, g_Kl);
    cudaGetSymbolAddress((void**)&Vh, g_Vh);   cudaGetSymbolAddress((void**)&Vl, g_Vl);
    cudaGetSymbolAddress((void**)&Ch, g_Ch);   cudaGetSymbolAddress((void**)&Cl, g_Cl);

    const int projSmem = 8 * PSZ * (int)sizeof(bf16);     // 81920
    const int attSmem  = 10 * QSZ * (int)sizeof(bf16);    // 184320

    static bool attr_set = false;
    if (!attr_set) {
        cudaFuncSetAttribute(k_proj3, cudaFuncAttributeMaxDynamicSharedMemorySize, projSmem);
        cudaFuncSetAttribute(k_projo, cudaFuncAttributeMaxDynamicSharedMemorySize, projSmem);
        cudaFuncSetAttribute(k_att,  cudaFuncAttributeMaxDynamicSharedMemorySize, attSmem);
        attr_set = true;
    }

    dim3 blk(256);

    // one batched conversion launch
    CvtArgs ca;
    ca.in[0] = tgt; ca.oh[0] = Th;  ca.ol[0] = Tl;  ca.n4[0] = BT * E_ / 4;
    ca.in[1] = src; ca.oh[1] = Sh;  ca.ol[1] = Sl;  ca.n4[1] = BT * E_ / 4;
    ca.in[2] = Wq;  ca.oh[2] = Wqh; ca.ol[2] = Wql; ca.n4[2] = E_ * E_ / 4;
    ca.in[3] = Wk;  ca.oh[3] = Wkh; ca.ol[3] = Wkl; ca.n4[3] = E_ * E_ / 4;
    ca.in[4] = Wv;  ca.oh[4] = Wvh; ca.ol[4] = Wvl; ca.n4[4] = E_ * E_ / 4;
    ca.in[5] = Wo;  ca.oh[5] = Woh; ca.ol[5] = Wol; ca.n4[5] = E_ * E_ / 4;
    k_cvt6<<<dim3((BT * E_ / 4 + 255) / 256, 1, 6), 256>>>(ca);

    k_proj3<<<dim3(E_ / 128, BT / 128, 3), blk, projSmem>>>(
        Th, Tl, Sh, Sl, Wqh, Wql, Wkh, Wkl, Wvh, Wvl,
        Qh, Ql, Kh, Kl, Vh, Vl);

    k_att<<<dim3(T_ / 128, Z_), blk, attSmem>>>(attn);

    k_projo<<<dim3(E_ / 128, BT / 128), blk, projSmem>>>(Ch, Cl, Woh, Wol, out, bo);
}